// round 2
// baseline (speedup 1.0000x reference)
#include <cuda_runtime.h>
#include <cuda_bf16.h>

// Problem dims (fixed by setup_inputs)
#define T_DIM 2048
#define N_DIM 128
#define C_DIM 96
#define L_DIM 200
#define S_EXT 401          // 2*L+1
#define NTHR  416          // 13 warps, one state per thread (401 real + 15 dummy)
#define PF    8            // log-prob register prefetch depth
#define NEGF  (-1.0e30f)   // log-domain 'zero' (absorption-safe in fp32)
#define LOG2E 1.44269504088896340736f
#define LN2   0.69314718055994530942f

__device__ float g_loss[N_DIM];

// One CTA per batch element. Log2-domain CTC forward (numerically safe:
// intra-vector dynamic range lives in the log values, not fp32 exponent).
// alpha ping-pong in SMEM, one barrier per time step.
__global__ __launch_bounds__(NTHR, 1)
void ctc_forward_kernel(const float* __restrict__ predicts,   // (T, N, C)
                        const int*   __restrict__ labels,     // (N, L)
                        const int*   __restrict__ preds_lengths,
                        const int*   __restrict__ label_lengths)
{
    const int s = threadIdx.x;
    const int n = blockIdx.x;

    __shared__ float As[2][NTHR + 4];   // [buf][s+2]; indices 0,1 are -inf pads
    __shared__ float Lp[2][C_DIM];      // log2-probs of current/next step
    __shared__ float Fin[2];

    // Extended label per state: even s -> blank(0), odd s -> labels[n][(s-1)/2].
    // Skip (s-2 -> s) allowed iff s odd, s>=3, label differs from previous label.
    int  ext  = 0;
    bool skip = false;
    if ((s & 1) && s < S_EXT) {
        const int k = s >> 1;
        ext = labels[n * L_DIM + k];
        if (s >= 3) skip = (ext != labels[n * L_DIM + k - 1]);
    }
    const int len = preds_lengths[n];
    const int end = 2 * label_lengths[n];

    if (s < 2) { As[0][s] = NEGF; As[1][s] = NEGF; }

    // Depth-PF register prefetch of this batch element's log-prob rows.
    const float* lpb = predicts + (size_t)n * C_DIM + s;
    float lpf[PF];
    if (s < C_DIM) {
#pragma unroll
        for (int j = 0; j < PF; ++j)
            lpf[j] = __ldg(lpb + (size_t)j * (N_DIM * C_DIM));
    }

    // log2-alpha, with virtual alpha_{-1}: 0 at s=0 (so t=0 gives standard init).
    float a    = (s == 0) ? 0.0f : NEGF;
    bool  done = false;

    for (int tt = 0; tt < T_DIM && !done; tt += PF) {
#pragma unroll
        for (int j = 0; j < PF; ++j) {
            const int t = tt + j;
            const int b = t & 1;

            if (s < C_DIM) {
                Lp[b][s] = lpf[j] * LOG2E;
                const int tn = t + PF;
                if (tn < T_DIM)
                    lpf[j] = __ldg(lpb + (size_t)tn * (N_DIM * C_DIM));
            }
            As[b][s + 2] = a;
            __syncthreads();

            const float am1 = As[b][s + 1];
            const float am2 = skip ? As[b][s] : NEGF;
            const float lpe = Lp[b][ext];

            // a = logaddexp2(a, am1, am2) + lpe
            const float m   = fmaxf(fmaxf(a, am1), am2);
            const float sum = exp2f(a - m) + exp2f(am1 - m) + exp2f(am2 - m);
            a = m + __log2f(sum) + lpe;

            if (t == len - 1) {
                if (s == end)     Fin[0] = a;
                if (s == end - 1) Fin[1] = a;
                __syncthreads();
                if (s == 0) {
                    const float f0 = Fin[0], f1 = Fin[1];
                    const float mm = fmaxf(f0, f1);
                    const float fin2 = mm + __log2f(exp2f(f0 - mm) + exp2f(f1 - mm));
                    const float ctc  = -(fin2 * LN2);
                    const float w    = 1.0f - __expf(-ctc);   // focal: alpha=1, gamma=2
                    g_loss[n] = ctc * (w * w);
                }
                done = true;
                break;
            }
        }
    }
}

// Reduce the 128 per-batch focal-weighted losses to the scalar output.
__global__ void ctc_finalize_kernel(float* __restrict__ out)
{
    const int i = threadIdx.x;
    float v = g_loss[i];
#pragma unroll
    for (int off = 16; off; off >>= 1)
        v += __shfl_xor_sync(0xffffffffu, v, off);
    __shared__ float ws[4];
    if ((i & 31) == 0) ws[i >> 5] = v;
    __syncthreads();
    if (i == 0) out[0] = ws[0] + ws[1] + ws[2] + ws[3];
}

extern "C" void kernel_launch(void* const* d_in, const int* in_sizes, int n_in,
                              void* d_out, int out_size)
{
    const float* predicts      = (const float*)d_in[0];
    const int*   labels        = (const int*)  d_in[1];
    // d_in[2] = ref_labels (unused), d_in[5] = ref_length (unused)
    const int*   preds_lengths = (const int*)  d_in[3];
    const int*   label_lengths = (const int*)  d_in[4];
    float*       out           = (float*)d_out;

    ctc_forward_kernel<<<N_DIM, NTHR>>>(predicts, labels, preds_lengths, label_lengths);
    ctc_finalize_kernel<<<1, N_DIM>>>(out);
}